// round 1
// baseline (speedup 1.0000x reference)
#include <cuda_runtime.h>
#include <math.h>

#define N_NODES 50000
#define FDIM    200
#define E1C     400000
#define E2C     100000
#define E_TOT   500000
#define ALPHA   0.2f

// ---- device scratch (no allocations allowed) ----
__device__ float g_X1[(size_t)N_NODES * FDIM];          // x @ A1^T
__device__ float g_X2[(size_t)N_NODES * FDIM];          // x @ A2^T
// g_accum layout: [0,10M) = ACC (sum e*X2[dst]); [10M,20M) = G (sum e*emb); [20M,20M+N) = rowsum
__device__ float g_accum[2 * (size_t)N_NODES * FDIM + N_NODES];
__device__ float g_p[4 * N_NODES];                      // p1, p2, pm1, pm2
__device__ float g_v[600];                              // a^T @ a_2
__device__ float g_w[600];                              // a^T @ mlp_w
__device__ float g_at[600 * FDIM];                      // a transposed: at[j*200+o] = a[o*600+j]

#define ACC_OFF  ((size_t)0)
#define G_OFF    ((size_t)N_NODES * FDIM)
#define RS_OFF   (2 * (size_t)N_NODES * FDIM)

__device__ __forceinline__ float dot4(float4 a, float4 b) {
    return a.x * b.x + a.y * b.y + a.z * b.z + a.w * b.w;
}

__device__ __forceinline__ void red_add_v4(float* addr, float4 v) {
    asm volatile("red.global.add.v4.f32 [%0], {%1,%2,%3,%4};"
                 :: "l"(addr), "f"(v.x), "f"(v.y), "f"(v.z), "f"(v.w)
                 : "memory");
}

// ---------------- zero scratch ----------------
__global__ __launch_bounds__(256) void zero_kernel(size_t n) {
    size_t i = (size_t)blockIdx.x * blockDim.x + threadIdx.x;
    if (i < n) g_accum[i] = 0.0f;
}

// ---------------- transpose a -> at ----------------
__global__ __launch_bounds__(256) void transpose_kernel(const float* __restrict__ a) {
    int i = blockIdx.x * blockDim.x + threadIdx.x;
    if (i < 600 * FDIM) {
        int j = i / FDIM;   // column of a (0..599)
        int o = i % FDIM;   // row of a (0..199)
        g_at[i] = a[o * 600 + j];
    }
}

// ---------------- v = a^T a_2, w = a^T mlp_w ----------------
__global__ __launch_bounds__(640) void vw_kernel(const float* __restrict__ a,
                                                 const float* __restrict__ a2,
                                                 const float* __restrict__ mw) {
    int j = threadIdx.x;
    if (j >= 600) return;
    float v = 0.f, w = 0.f;
    for (int o = 0; o < FDIM; o++) {
        float aj = a[o * 600 + j];
        float s2 = a2[o];
        float sm = mw[o];
        v += aj * s2;
        w += aj * sm;
    }
    g_v[j] = v;
    g_w[j] = w;
}

// ---------------- per-node scalar projections ----------------
// p1[n] = x[n].v[0:200], p2[n] = x[n].v[200:400], pm1/pm2 with w
__global__ __launch_bounds__(256) void pvec_kernel(const float* __restrict__ x) {
    __shared__ float4 sv[100];  // g_v[0:400]
    __shared__ float4 sw[100];  // g_w[0:400]
    int t = threadIdx.x;
    if (t < 100)       sv[t]       = ((const float4*)g_v)[t];
    else if (t < 200)  sw[t - 100] = ((const float4*)g_w)[t - 100];
    __syncthreads();

    int warp = t >> 5, lane = t & 31;
    int node = blockIdx.x * 8 + warp;
    if (node >= N_NODES) return;

    const float4* xr = (const float4*)x + (size_t)node * 50;
    float4 x0 = xr[lane];
    float4 x1 = (lane < 18) ? xr[32 + lane] : make_float4(0, 0, 0, 0);

    float p1  = dot4(x0, sv[lane])      + ((lane < 18) ? dot4(x1, sv[32 + lane]) : 0.f);
    float p2  = dot4(x0, sv[50 + lane]) + ((lane < 18) ? dot4(x1, sv[82 + lane]) : 0.f);
    float pm1 = dot4(x0, sw[lane])      + ((lane < 18) ? dot4(x1, sw[32 + lane]) : 0.f);
    float pm2 = dot4(x0, sw[50 + lane]) + ((lane < 18) ? dot4(x1, sw[82 + lane]) : 0.f);

    #pragma unroll
    for (int off = 16; off; off >>= 1) {
        p1  += __shfl_xor_sync(0xffffffffu, p1, off);
        p2  += __shfl_xor_sync(0xffffffffu, p2, off);
        pm1 += __shfl_xor_sync(0xffffffffu, pm1, off);
        pm2 += __shfl_xor_sync(0xffffffffu, pm2, off);
    }
    if (lane == 0) {
        g_p[node]               = p1;
        g_p[N_NODES + node]     = p2;
        g_p[2 * N_NODES + node] = pm1;
        g_p[3 * N_NODES + node] = pm2;
    }
}

// ---------------- GEMM: C[M,200] = In[M,200] @ at[at_off : at_off+200]^(slab) ----------------
// dest: 0 -> g_X1, 1 -> g_X2, 2 -> epilogue into fout (attention output)
__global__ __launch_bounds__(256) void gemm_kernel(const float* __restrict__ in,
                                                   int M, int at_off, int dest,
                                                   float* __restrict__ fout) {
    __shared__ float As[8][64];
    __shared__ float Bs[8][64];
    const float* In = (dest == 2) ? (g_accum + G_OFF) : in;
    int row0 = blockIdx.x * 64;
    int col0 = blockIdx.y * 64;
    int t = threadIdx.x;
    int tx = t & 15, ty = t >> 4;
    float acc[4][4] = {};

    for (int kb = 0; kb < FDIM; kb += 8) {
        #pragma unroll
        for (int l = t; l < 512; l += 256) {
            int m = l >> 3, k = l & 7;
            int r = row0 + m;
            As[k][m] = (r < M) ? In[(size_t)r * FDIM + kb + k] : 0.f;
        }
        #pragma unroll
        for (int l = t; l < 512; l += 256) {
            int c = l & 63, k = l >> 6;
            int cc = col0 + c;
            Bs[k][c] = (cc < FDIM) ? g_at[(at_off + kb + k) * FDIM + cc] : 0.f;
        }
        __syncthreads();
        #pragma unroll
        for (int k = 0; k < 8; k++) {
            float4 av = *(const float4*)&As[k][ty * 4];
            float4 bv = *(const float4*)&Bs[k][tx * 4];
            float a4[4] = {av.x, av.y, av.z, av.w};
            float b4[4] = {bv.x, bv.y, bv.z, bv.w};
            #pragma unroll
            for (int i = 0; i < 4; i++)
                #pragma unroll
                for (int j = 0; j < 4; j++)
                    acc[i][j] += a4[i] * b4[j];
        }
        __syncthreads();
    }

    if (dest != 2) {
        float* Out = (dest == 0) ? g_X1 : g_X2;
        #pragma unroll
        for (int i = 0; i < 4; i++) {
            int r = row0 + ty * 4 + i;
            if (r >= M) continue;
            #pragma unroll
            for (int j = 0; j < 4; j++) {
                int c = col0 + tx * 4 + j;
                if (c < FDIM) Out[(size_t)r * FDIM + c] = acc[i][j];
            }
        }
    } else {
        const float* rows = g_accum + RS_OFF;
        #pragma unroll
        for (int i = 0; i < 4; i++) {
            int r = row0 + ty * 4 + i;
            if (r >= M) continue;
            float rs = rows[r];
            float inv = (rs == 0.f) ? 0.f : 1.f / rs;
            #pragma unroll
            for (int j = 0; j < 4; j++) {
                int c = col0 + tx * 4 + j;
                if (c >= FDIM) continue;
                float o;
                if (rs == 0.f) {
                    o = 0.f;  // reference: h' = 0/1e-12 = 0, elu(0) = 0
                } else {
                    size_t idx = (size_t)r * FDIM + c;
                    float v = g_X1[idx] + (g_accum[ACC_OFF + idx] + acc[i][j]) * inv;
                    o = (v > 0.f) ? v : (expf(v) - 1.f);  // elu
                }
                fout[(size_t)r * FDIM + c] = o;
            }
        }
    }
}

// ---------------- per-edge kernel ----------------
__global__ __launch_bounds__(256) void edge_kernel(const int* __restrict__ edge,
                                                   const float* __restrict__ emb1,
                                                   const int* __restrict__ edge2,
                                                   const float* __restrict__ emb2,
                                                   const float* __restrict__ mlp_b) {
    __shared__ float4 sv[50];  // v3 = g_v[400:600]
    __shared__ float4 sw[50];  // w3 = g_w[400:600]
    int t = threadIdx.x;
    if (t < 50)       sv[t]      = *(const float4*)&g_v[400 + t * 4];
    else if (t < 100) sw[t - 50] = *(const float4*)&g_w[400 + (t - 50) * 4];
    __syncthreads();

    int warp = t >> 5, lane = t & 31;
    int eid = blockIdx.x * 8 + warp;
    if (eid >= E_TOT) return;

    int src, dst;
    const float4* emb;
    if (eid < E1C) {
        src = edge[eid];
        dst = edge[E1C + eid];
        emb = (const float4*)(emb1 + (size_t)eid * FDIM);
    } else {
        int e2 = eid - E1C;
        src = edge2[e2];
        dst = edge2[E2C + e2];
        emb = (const float4*)(emb2 + (size_t)e2 * FDIM);
    }

    float4 m0 = emb[lane];
    float4 m1 = (lane < 18) ? emb[32 + lane] : make_float4(0, 0, 0, 0);

    float q3 = dot4(m0, sv[lane]) + ((lane < 18) ? dot4(m1, sv[32 + lane]) : 0.f);
    float qm = dot4(m0, sw[lane]) + ((lane < 18) ? dot4(m1, sw[32 + lane]) : 0.f);
    #pragma unroll
    for (int off = 16; off; off >>= 1) {
        q3 += __shfl_xor_sync(0xffffffffu, q3, off);
        qm += __shfl_xor_sync(0xffffffffu, qm, off);
    }

    float sa = g_p[src] + g_p[N_NODES + dst] + q3;
    float sm = g_p[2 * N_NODES + src] + g_p[3 * N_NODES + dst] + qm + mlp_b[0];
    float lr = (sa > 0.f) ? sa : ALPHA * sa;
    float pw = -lr * tanhf(sm) * (1.0f / (float)E_TOT);
    float ee = expf(pw);

    const float4* x2 = (const float4*)g_X2 + (size_t)dst * 50;
    float* Gp = g_accum + G_OFF + (size_t)src * FDIM;
    float* Ap = g_accum + ACC_OFF + (size_t)src * FDIM;

    float4 xa = x2[lane];
    red_add_v4(Gp + lane * 4, make_float4(ee * m0.x, ee * m0.y, ee * m0.z, ee * m0.w));
    red_add_v4(Ap + lane * 4, make_float4(ee * xa.x, ee * xa.y, ee * xa.z, ee * xa.w));
    if (lane < 18) {
        float4 xb = x2[32 + lane];
        red_add_v4(Gp + (32 + lane) * 4, make_float4(ee * m1.x, ee * m1.y, ee * m1.z, ee * m1.w));
        red_add_v4(Ap + (32 + lane) * 4, make_float4(ee * xb.x, ee * xb.y, ee * xb.z, ee * xb.w));
    }
    if (lane == 0) atomicAdd(g_accum + RS_OFF + src, ee);
}

extern "C" void kernel_launch(void* const* d_in, const int* in_sizes, int n_in,
                              void* d_out, int out_size) {
    const float* x    = (const float*)d_in[0];
    const int*   edge = (const int*)  d_in[1];
    const float* ee1  = (const float*)d_in[2];
    const int*   edg2 = (const int*)  d_in[3];
    const float* ee2  = (const float*)d_in[4];
    const float* a    = (const float*)d_in[5];
    const float* a2   = (const float*)d_in[6];
    const float* mw   = (const float*)d_in[7];
    const float* mb   = (const float*)d_in[8];
    float* out = (float*)d_out;

    size_t nz = 2 * (size_t)N_NODES * FDIM + N_NODES;
    zero_kernel<<<(unsigned)((nz + 255) / 256), 256>>>(nz);
    transpose_kernel<<<(600 * FDIM + 255) / 256, 256>>>(a);
    vw_kernel<<<1, 640>>>(a, a2, mw);
    pvec_kernel<<<N_NODES / 8, 256>>>(x);

    dim3 ggrid((N_NODES + 63) / 64, (FDIM + 63) / 64);
    gemm_kernel<<<ggrid, 256>>>(x, N_NODES, 0, 0, nullptr);    // X1
    gemm_kernel<<<ggrid, 256>>>(x, N_NODES, 200, 1, nullptr);  // X2

    edge_kernel<<<E_TOT / 8, 256>>>(edge, ee1, edg2, ee2, mb);

    gemm_kernel<<<ggrid, 256>>>(nullptr, N_NODES, 400, 2, out);  // G@A3^T + epilogue
}

// round 2
// speedup vs baseline: 1.2132x; 1.2132x over previous
#include <cuda_runtime.h>
#include <math.h>
#include <stdint.h>

#define N_NODES 50000
#define FDIM    200
#define E1C     400000
#define E2C     100000
#define E_TOT   500000
#define ALPHA   0.2f

// tensor-GEMM tiling
#define BM 128
#define BK 40
#define NKB 5                 // 200 / 40
#define AS_STRIDE 136         // 136 mod 32 == 8 -> conflict-free A frag loads
#define BS_STRIDE 200         // 200 mod 32 == 8 -> conflict-free B frag loads
#define SMEM_FLOATS (2*BK*AS_STRIDE + 2*BK*BS_STRIDE)
#define SMEM_BYTES  (SMEM_FLOATS * 4)

// ---- device scratch (no allocations allowed) ----
__device__ float g_X1[(size_t)N_NODES * FDIM];          // x @ A1^T
__device__ float g_X2[(size_t)N_NODES * FDIM];          // x @ A2^T
// g_accum: [0,10M) = ACC (sum e*X2[dst]); [10M,20M) = G (sum e*emb); [20M,20M+N) = rowsum
__device__ float g_accum[2 * (size_t)N_NODES * FDIM + N_NODES];
__device__ float g_p[4 * N_NODES];                      // p1, p2, pm1, pm2
__device__ float g_v[600];                              // a^T @ a_2
__device__ float g_w[600];                              // a^T @ mlp_w
__device__ float g_at[600 * FDIM];                      // at[j*200+o] = a[o*600+j]

#define ACC_OFF  ((size_t)0)
#define G_OFF    ((size_t)N_NODES * FDIM)
#define RS_OFF   (2 * (size_t)N_NODES * FDIM)

__device__ __forceinline__ float dot4(float4 a, float4 b) {
    return a.x * b.x + a.y * b.y + a.z * b.z + a.w * b.w;
}

__device__ __forceinline__ void red_add_v4(float* addr, float4 v) {
    asm volatile("red.global.add.v4.f32 [%0], {%1,%2,%3,%4};"
                 :: "l"(addr), "f"(v.x), "f"(v.y), "f"(v.z), "f"(v.w)
                 : "memory");
}

__device__ __forceinline__ float to_tf32(float x) {
    uint32_t u;
    asm("cvt.rna.tf32.f32 %0, %1;" : "=r"(u) : "f"(x));
    return __uint_as_float(u);
}

__device__ __forceinline__ void mma_tf32(float* c, const uint32_t* a, uint32_t b0, uint32_t b1) {
    asm volatile("mma.sync.aligned.m16n8k8.row.col.f32.tf32.tf32.f32 "
                 "{%0,%1,%2,%3}, {%4,%5,%6,%7}, {%8,%9}, {%0,%1,%2,%3};"
                 : "+f"(c[0]), "+f"(c[1]), "+f"(c[2]), "+f"(c[3])
                 : "r"(a[0]), "r"(a[1]), "r"(a[2]), "r"(a[3]), "r"(b0), "r"(b1));
}

// ---------------- zero scratch ----------------
__global__ __launch_bounds__(256) void zero_kernel(size_t n) {
    size_t i = (size_t)blockIdx.x * blockDim.x + threadIdx.x;
    if (i < n) g_accum[i] = 0.0f;
}

// ---------------- transpose a -> at ----------------
__global__ __launch_bounds__(256) void transpose_kernel(const float* __restrict__ a) {
    int i = blockIdx.x * blockDim.x + threadIdx.x;
    if (i < 600 * FDIM) {
        int j = i / FDIM;
        int o = i % FDIM;
        g_at[i] = a[o * 600 + j];
    }
}

// ---------------- v = a^T a_2, w = a^T mlp_w ----------------
__global__ __launch_bounds__(640) void vw_kernel(const float* __restrict__ a,
                                                 const float* __restrict__ a2,
                                                 const float* __restrict__ mw) {
    int j = threadIdx.x;
    if (j >= 600) return;
    float v = 0.f, w = 0.f;
    for (int o = 0; o < FDIM; o++) {
        float aj = a[o * 600 + j];
        v += aj * a2[o];
        w += aj * mw[o];
    }
    g_v[j] = v;
    g_w[j] = w;
}

// ---------------- per-node scalar projections ----------------
__global__ __launch_bounds__(256) void pvec_kernel(const float* __restrict__ x) {
    __shared__ float4 sv[100];
    __shared__ float4 sw[100];
    int t = threadIdx.x;
    if (t < 100)       sv[t]       = ((const float4*)g_v)[t];
    else if (t < 200)  sw[t - 100] = ((const float4*)g_w)[t - 100];
    __syncthreads();

    int warp = t >> 5, lane = t & 31;
    int node = blockIdx.x * 8 + warp;
    if (node >= N_NODES) return;

    const float4* xr = (const float4*)x + (size_t)node * 50;
    float4 x0 = xr[lane];
    float4 x1 = (lane < 18) ? xr[32 + lane] : make_float4(0, 0, 0, 0);

    float p1  = dot4(x0, sv[lane])      + ((lane < 18) ? dot4(x1, sv[32 + lane]) : 0.f);
    float p2  = dot4(x0, sv[50 + lane]) + ((lane < 18) ? dot4(x1, sv[82 + lane]) : 0.f);
    float pm1 = dot4(x0, sw[lane])      + ((lane < 18) ? dot4(x1, sw[32 + lane]) : 0.f);
    float pm2 = dot4(x0, sw[50 + lane]) + ((lane < 18) ? dot4(x1, sw[82 + lane]) : 0.f);

    #pragma unroll
    for (int off = 16; off; off >>= 1) {
        p1  += __shfl_xor_sync(0xffffffffu, p1, off);
        p2  += __shfl_xor_sync(0xffffffffu, p2, off);
        pm1 += __shfl_xor_sync(0xffffffffu, pm1, off);
        pm2 += __shfl_xor_sync(0xffffffffu, pm2, off);
    }
    if (lane == 0) {
        g_p[node]               = p1;
        g_p[N_NODES + node]     = p2;
        g_p[2 * N_NODES + node] = pm1;
        g_p[3 * N_NODES + node] = pm2;
    }
}

// ---------------- tensor-core GEMM (3xTF32): C[M,200] = In @ at_slab^T ----------------
// dest: 0 -> g_X1, 1 -> g_X2, 2 -> epilogue into fout
__global__ void __launch_bounds__(256, 1)
tgemm_kernel(const float* __restrict__ in, int M, int at_off, int dest,
             float* __restrict__ fout) {
    extern __shared__ float sm_[];
    float* As_hi = sm_;
    float* As_lo = As_hi + BK * AS_STRIDE;
    float* Bs_hi = As_lo + BK * AS_STRIDE;
    float* Bs_lo = Bs_hi + BK * BS_STRIDE;

    const float* In = (dest == 2) ? (g_accum + G_OFF) : in;
    int row0 = blockIdx.x * BM;
    int t = threadIdx.x;
    int warp = t >> 5, lane = t & 31;
    int mg = warp >> 1;            // 0..3 -> m offset mg*32
    int ng = warp & 1;             // 0..1 -> n offset ng*96 (13 tiles, middle tile overlaps)
    int n0 = ng * 96;
    int m0w = mg * 32;
    int lr = lane >> 2;            // 0..7
    int lc = lane & 3;             // 0..3

    float acc[2][13][4];
    #pragma unroll
    for (int a_ = 0; a_ < 2; a_++)
        #pragma unroll
        for (int b_ = 0; b_ < 13; b_++)
            #pragma unroll
            for (int c_ = 0; c_ < 4; c_++) acc[a_][b_][c_] = 0.f;

    for (int kb = 0; kb < NKB; kb++) {
        int k0 = kb * BK;
        __syncthreads();
        // stage A: 128 rows x 40 cols = 1280 float4
        #pragma unroll
        for (int i = 0; i < 5; i++) {
            int idx = t + i * 256;
            int r = idx / 10, c4 = idx % 10;
            float4 v = make_float4(0, 0, 0, 0);
            if (row0 + r < M)
                v = *(const float4*)(In + (size_t)(row0 + r) * FDIM + k0 + c4 * 4);
            float vv[4] = {v.x, v.y, v.z, v.w};
            #pragma unroll
            for (int j = 0; j < 4; j++) {
                float hi = to_tf32(vv[j]);
                float lo = to_tf32(vv[j] - hi);
                int k = c4 * 4 + j;
                As_hi[k * AS_STRIDE + r] = hi;
                As_lo[k * AS_STRIDE + r] = lo;
            }
        }
        // stage B: 40 rows x 200 cols = 2000 float4
        #pragma unroll
        for (int i = 0; i < 8; i++) {
            int idx = t + i * 256;
            if (idx < 2000) {
                int r = idx / 50, c4 = idx % 50;
                float4 v = *(const float4*)(g_at + (size_t)(at_off + k0 + r) * FDIM + c4 * 4);
                float vv[4] = {v.x, v.y, v.z, v.w};
                #pragma unroll
                for (int j = 0; j < 4; j++) {
                    float hi = to_tf32(vv[j]);
                    float lo = to_tf32(vv[j] - hi);
                    Bs_hi[r * BS_STRIDE + c4 * 4 + j] = hi;
                    Bs_lo[r * BS_STRIDE + c4 * 4 + j] = lo;
                }
            }
        }
        __syncthreads();

        #pragma unroll
        for (int kk = 0; kk < 5; kk++) {
            int ks = kk * 8;
            uint32_t ah[2][4], al[2][4];
            #pragma unroll
            for (int mt = 0; mt < 2; mt++) {
                int mrow = m0w + mt * 16 + lr;
                ah[mt][0] = __float_as_uint(As_hi[(ks + lc) * AS_STRIDE + mrow]);
                ah[mt][1] = __float_as_uint(As_hi[(ks + lc) * AS_STRIDE + mrow + 8]);
                ah[mt][2] = __float_as_uint(As_hi[(ks + lc + 4) * AS_STRIDE + mrow]);
                ah[mt][3] = __float_as_uint(As_hi[(ks + lc + 4) * AS_STRIDE + mrow + 8]);
                al[mt][0] = __float_as_uint(As_lo[(ks + lc) * AS_STRIDE + mrow]);
                al[mt][1] = __float_as_uint(As_lo[(ks + lc) * AS_STRIDE + mrow + 8]);
                al[mt][2] = __float_as_uint(As_lo[(ks + lc + 4) * AS_STRIDE + mrow]);
                al[mt][3] = __float_as_uint(As_lo[(ks + lc + 4) * AS_STRIDE + mrow + 8]);
            }
            #pragma unroll
            for (int nt = 0; nt < 13; nt++) {
                int nc = n0 + nt * 8 + lr;
                uint32_t bh0 = __float_as_uint(Bs_hi[(ks + lc) * BS_STRIDE + nc]);
                uint32_t bh1 = __float_as_uint(Bs_hi[(ks + lc + 4) * BS_STRIDE + nc]);
                uint32_t bl0 = __float_as_uint(Bs_lo[(ks + lc) * BS_STRIDE + nc]);
                uint32_t bl1 = __float_as_uint(Bs_lo[(ks + lc + 4) * BS_STRIDE + nc]);
                #pragma unroll
                for (int mt = 0; mt < 2; mt++) {
                    mma_tf32(acc[mt][nt], ah[mt], bh0, bh1);
                    mma_tf32(acc[mt][nt], ah[mt], bl0, bl1);
                    mma_tf32(acc[mt][nt], al[mt], bh0, bh1);
                }
            }
        }
    }

    // ---- store ----
    if (dest != 2) {
        float* Out = (dest == 0) ? g_X1 : g_X2;
        #pragma unroll
        for (int mt = 0; mt < 2; mt++) {
            int r0 = row0 + m0w + mt * 16 + lr;
            #pragma unroll
            for (int nt = 0; nt < 13; nt++) {
                int col = n0 + nt * 8 + 2 * lc;
                if (r0 < M)
                    *(float2*)(Out + (size_t)r0 * FDIM + col) =
                        make_float2(acc[mt][nt][0], acc[mt][nt][1]);
                if (r0 + 8 < M)
                    *(float2*)(Out + (size_t)(r0 + 8) * FDIM + col) =
                        make_float2(acc[mt][nt][2], acc[mt][nt][3]);
            }
        }
    } else {
        const float* rows = g_accum + RS_OFF;
        #pragma unroll
        for (int mt = 0; mt < 2; mt++) {
            #pragma unroll
            for (int h = 0; h < 2; h++) {
                int r = row0 + m0w + mt * 16 + lr + 8 * h;
                if (r >= M) continue;
                float rs = rows[r];
                if (rs == 0.f) {
                    #pragma unroll
                    for (int nt = 0; nt < 13; nt++) {
                        int col = n0 + nt * 8 + 2 * lc;
                        *(float2*)(fout + (size_t)r * FDIM + col) = make_float2(0.f, 0.f);
                    }
                } else {
                    float inv = 1.f / rs;
                    #pragma unroll
                    for (int nt = 0; nt < 13; nt++) {
                        int col = n0 + nt * 8 + 2 * lc;
                        size_t idx = (size_t)r * FDIM + col;
                        float2 x1 = *(const float2*)(g_X1 + idx);
                        float2 av = *(const float2*)(g_accum + ACC_OFF + idx);
                        float g0 = acc[mt][nt][2 * h + 0];
                        float g1 = acc[mt][nt][2 * h + 1];
                        float v0 = x1.x + (av.x + g0) * inv;
                        float v1 = x1.y + (av.y + g1) * inv;
                        v0 = (v0 > 0.f) ? v0 : (expf(v0) - 1.f);
                        v1 = (v1 > 0.f) ? v1 : (expf(v1) - 1.f);
                        *(float2*)(fout + idx) = make_float2(v0, v1);
                    }
                }
            }
        }
    }
}

// ---------------- per-edge kernel ----------------
__global__ __launch_bounds__(256) void edge_kernel(const int* __restrict__ edge,
                                                   const float* __restrict__ emb1,
                                                   const int* __restrict__ edge2,
                                                   const float* __restrict__ emb2,
                                                   const float* __restrict__ mlp_b) {
    __shared__ float4 sv[50];
    __shared__ float4 sw[50];
    int t = threadIdx.x;
    if (t < 50)       sv[t]      = *(const float4*)&g_v[400 + t * 4];
    else if (t < 100) sw[t - 50] = *(const float4*)&g_w[400 + (t - 50) * 4];
    __syncthreads();

    int warp = t >> 5, lane = t & 31;
    int eid = blockIdx.x * 8 + warp;
    if (eid >= E_TOT) return;

    int src, dst;
    const float4* emb;
    if (eid < E1C) {
        src = edge[eid];
        dst = edge[E1C + eid];
        emb = (const float4*)(emb1 + (size_t)eid * FDIM);
    } else {
        int e2 = eid - E1C;
        src = edge2[e2];
        dst = edge2[E2C + e2];
        emb = (const float4*)(emb2 + (size_t)e2 * FDIM);
    }

    float4 m0 = emb[lane];
    float4 m1 = (lane < 18) ? emb[32 + lane] : make_float4(0, 0, 0, 0);

    float q3 = dot4(m0, sv[lane]) + ((lane < 18) ? dot4(m1, sv[32 + lane]) : 0.f);
    float qm = dot4(m0, sw[lane]) + ((lane < 18) ? dot4(m1, sw[32 + lane]) : 0.f);
    #pragma unroll
    for (int off = 16; off; off >>= 1) {
        q3 += __shfl_xor_sync(0xffffffffu, q3, off);
        qm += __shfl_xor_sync(0xffffffffu, qm, off);
    }

    float sa = g_p[src] + g_p[N_NODES + dst] + q3;
    float sm = g_p[2 * N_NODES + src] + g_p[3 * N_NODES + dst] + qm + mlp_b[0];
    float lrv = (sa > 0.f) ? sa : ALPHA * sa;
    float pw = -lrv * tanhf(sm) * (1.0f / (float)E_TOT);
    float ee = expf(pw);

    const float4* x2 = (const float4*)g_X2 + (size_t)dst * 50;
    float* Gp = g_accum + G_OFF + (size_t)src * FDIM;
    float* Ap = g_accum + ACC_OFF + (size_t)src * FDIM;

    float4 xa = x2[lane];
    red_add_v4(Gp + lane * 4, make_float4(ee * m0.x, ee * m0.y, ee * m0.z, ee * m0.w));
    red_add_v4(Ap + lane * 4, make_float4(ee * xa.x, ee * xa.y, ee * xa.z, ee * xa.w));
    if (lane < 18) {
        float4 xb = x2[32 + lane];
        red_add_v4(Gp + (32 + lane) * 4, make_float4(ee * m1.x, ee * m1.y, ee * m1.z, ee * m1.w));
        red_add_v4(Ap + (32 + lane) * 4, make_float4(ee * xb.x, ee * xb.y, ee * xb.z, ee * xb.w));
    }
    if (lane == 0) atomicAdd(g_accum + RS_OFF + src, ee);
}

extern "C" void kernel_launch(void* const* d_in, const int* in_sizes, int n_in,
                              void* d_out, int out_size) {
    const float* x    = (const float*)d_in[0];
    const int*   edge = (const int*)  d_in[1];
    const float* ee1  = (const float*)d_in[2];
    const int*   edg2 = (const int*)  d_in[3];
    const float* ee2  = (const float*)d_in[4];
    const float* a    = (const float*)d_in[5];
    const float* a2   = (const float*)d_in[6];
    const float* mw   = (const float*)d_in[7];
    const float* mb   = (const float*)d_in[8];
    float* out = (float*)d_out;

    cudaFuncSetAttribute(tgemm_kernel, cudaFuncAttributeMaxDynamicSharedMemorySize, SMEM_BYTES);

    size_t nz = 2 * (size_t)N_NODES * FDIM + N_NODES;
    zero_kernel<<<(unsigned)((nz + 255) / 256), 256>>>(nz);
    transpose_kernel<<<(600 * FDIM + 255) / 256, 256>>>(a);
    vw_kernel<<<1, 640>>>(a, a2, mw);
    pvec_kernel<<<N_NODES / 8, 256>>>(x);

    int ggrid = (N_NODES + BM - 1) / BM;
    tgemm_kernel<<<ggrid, 256, SMEM_BYTES>>>(x, N_NODES, 0, 0, nullptr);    // X1
    tgemm_kernel<<<ggrid, 256, SMEM_BYTES>>>(x, N_NODES, 200, 1, nullptr);  // X2

    edge_kernel<<<E_TOT / 8, 256>>>(edge, ee1, edg2, ee2, mb);

    tgemm_kernel<<<ggrid, 256, SMEM_BYTES>>>(nullptr, N_NODES, 400, 2, out);  // G@A3^T + epilogue
}